// round 2
// baseline (speedup 1.0000x reference)
#include <cuda_runtime.h>
#include <cstdint>

#define N_NODES 100000
#define N_EDGES 3200000
#define N_FEAT  512
#define N_DIMS  256
#define N_CLSS  10

// ---------------- scratch (device globals: no allocation allowed) ----------
__device__ float g_h[(size_t)N_NODES * N_DIMS];   // GEMM outputs (h1 / h2)
__device__ float g_a[(size_t)N_NODES * N_DIMS];   // aggregated + relu activations
__device__ float g_dinv[N_NODES];                 // degree, then d^-1/2 in place
__device__ float g_norm[N_EDGES];
__device__ int   g_row[N_EDGES];
__device__ int   g_col[N_EDGES];
__device__ int   g_rowptr[N_NODES + 1];           // CSR by destination (col)
__device__ int   g_cnt[N_NODES];
__device__ int   g_eidx[N_EDGES];
__device__ int   g_blksum[128];

static const int SCAN_NBLK = (N_NODES + 1023) / 1024;   // 98

// ---------------- f32x2 helpers --------------------------------------------
__device__ __forceinline__ unsigned long long splat2(float x) {
    unsigned long long r;
    asm("mov.b64 %0, {%1,%1};" : "=l"(r) : "f"(x));
    return r;
}
__device__ __forceinline__ void fma2(unsigned long long& c,
                                     unsigned long long a,
                                     unsigned long long b) {
    asm("fma.rn.f32x2 %0, %1, %2, %3;" : "=l"(c) : "l"(a), "l"(b), "l"(c));
}
__device__ __forceinline__ float2 unpack2(unsigned long long v) {
    float2 f;
    asm("mov.b64 {%0,%1}, %2;" : "=f"(f.x), "=f"(f.y) : "l"(v));
    return f;
}

// ---------------- preprocessing --------------------------------------------
__global__ void init_kernel() {
    int i = blockIdx.x * blockDim.x + threadIdx.x;
    if (i < N_NODES) {
        g_dinv[i] = 1.0f;   // self-loop weight 1 contributes to degree
        g_cnt[i]  = 0;
    }
}

// edge_index is int32: JAX with default config (x64 disabled) downcasts
// jnp.int64 requests to int32 silently.
__global__ void edge_pass1(const int* __restrict__ ei,
                           const float* __restrict__ ew) {
    int e = blockIdx.x * blockDim.x + threadIdx.x;
    if (e >= N_EDGES) return;
    int r = ei[e];
    int c = ei[N_EDGES + e];
    g_row[e] = r;
    g_col[e] = c;
    atomicAdd(&g_dinv[c], ew[e]);
    atomicAdd(&g_cnt[c], 1);
}

__global__ void dinv_kernel() {
    int i = blockIdx.x * blockDim.x + threadIdx.x;
    if (i < N_NODES) {
        float d = g_dinv[i];
        g_dinv[i] = (d > 0.0f) ? rsqrtf(d) : 0.0f;
    }
}

__global__ void norm_kernel(const float* __restrict__ ew) {
    int e = blockIdx.x * blockDim.x + threadIdx.x;
    if (e >= N_EDGES) return;
    g_norm[e] = g_dinv[g_row[e]] * ew[e] * g_dinv[g_col[e]];
}

// ---- 2-level exclusive scan of g_cnt into g_rowptr ----
__global__ void scanA_kernel() {
    __shared__ int sm[256];
    int b = blockIdx.x, t = threadIdx.x;
    int base = b * 1024 + t * 4;
    int v0 = (base + 0 < N_NODES) ? g_cnt[base + 0] : 0;
    int v1 = (base + 1 < N_NODES) ? g_cnt[base + 1] : 0;
    int v2 = (base + 2 < N_NODES) ? g_cnt[base + 2] : 0;
    int v3 = (base + 3 < N_NODES) ? g_cnt[base + 3] : 0;
    v1 += v0; v2 += v1; v3 += v2;
    sm[t] = v3;
    __syncthreads();
    #pragma unroll
    for (int off = 1; off < 256; off <<= 1) {
        int x = (t >= off) ? sm[t - off] : 0;
        __syncthreads();
        sm[t] += x;
        __syncthreads();
    }
    int excl = sm[t] - v3;
    if (base + 0 < N_NODES) g_rowptr[base + 1] = v0 + excl;
    if (base + 1 < N_NODES) g_rowptr[base + 2] = v1 + excl;
    if (base + 2 < N_NODES) g_rowptr[base + 3] = v2 + excl;
    if (base + 3 < N_NODES) g_rowptr[base + 4] = v3 + excl;
    if (t == 255) g_blksum[b] = sm[255];
}

__global__ void scanB_kernel(int nblk) {
    // single thread: serial exclusive scan of <=128 block sums
    int run = 0;
    for (int i = 0; i < nblk; i++) {
        int v = g_blksum[i];
        g_blksum[i] = run;
        run += v;
    }
}

__global__ void scanC_kernel() {
    int i = blockIdx.x * blockDim.x + threadIdx.x;
    if (i < N_NODES) {
        g_rowptr[i + 1] += g_blksum[i >> 10];
        g_cnt[i] = 0;                 // reset for pass2 fill
        if (i == 0) g_rowptr[0] = 0;
    }
}

__global__ void edge_pass2() {
    int e = blockIdx.x * blockDim.x + threadIdx.x;
    if (e >= N_EDGES) return;
    int c = g_col[e];
    int p = g_rowptr[c] + atomicAdd(&g_cnt[c], 1);
    g_eidx[p] = e;
}

// ---------------- GEMM: C(g_h)[M,256] = A[M,K] @ W[K,256] ------------------
// SRC == 0: A = external input (x); SRC == 1: A = g_a
template <int K, int SRC>
__global__ void __launch_bounds__(256, 2)
gemm_kernel(const float* __restrict__ Ain, const float* __restrict__ W) {
    const float* __restrict__ A = (SRC == 0) ? Ain : (const float*)g_a;
    constexpr int BM = 64, BK = 16;
    __shared__ __align__(16) float As[BK][BM];       // k-major for broadcast reads
    __shared__ __align__(16) float Ws[BK][N_DIMS];

    const int t  = threadIdx.x;
    const int ty = t >> 5;     // 0..7  -> 8-row group
    const int tx = t & 31;     // 0..31 -> 8-col group
    const int row0 = blockIdx.x * BM;

    unsigned long long acc[8][4];
    #pragma unroll
    for (int i = 0; i < 8; i++)
        #pragma unroll
        for (int j = 0; j < 4; j++) acc[i][j] = 0ull;

    const int ra = t >> 2;            // 0..63 : A row within tile
    const int ka = (t & 3) << 2;      // 0,4,8,12 : k offset

    for (int kt = 0; kt < K; kt += BK) {
        float4 av = make_float4(0.f, 0.f, 0.f, 0.f);
        if (row0 + ra < N_NODES)
            av = *(const float4*)&A[(size_t)(row0 + ra) * K + kt + ka];
        As[ka + 0][ra] = av.x;
        As[ka + 1][ra] = av.y;
        As[ka + 2][ra] = av.z;
        As[ka + 3][ra] = av.w;
        #pragma unroll
        for (int i = 0; i < 4; i++) {
            int p  = t + i * 256;         // float4 id within 16x256 tile
            int kk = p >> 6;
            int cc = (p & 63) << 2;
            *(float4*)&Ws[kk][cc] =
                *(const float4*)&W[(size_t)(kt + kk) * N_DIMS + cc];
        }
        __syncthreads();

        #pragma unroll
        for (int k = 0; k < BK; k++) {
            float4 a0 = *(const float4*)&As[k][ty * 8];
            float4 a1 = *(const float4*)&As[k][ty * 8 + 4];
            const ulonglong2* wp = (const ulonglong2*)&Ws[k][tx * 8];
            ulonglong2 wv0 = wp[0], wv1 = wp[1];
            unsigned long long w0 = wv0.x, w1 = wv0.y, w2 = wv1.x, w3 = wv1.y;
            unsigned long long ar[8];
            ar[0] = splat2(a0.x); ar[1] = splat2(a0.y);
            ar[2] = splat2(a0.z); ar[3] = splat2(a0.w);
            ar[4] = splat2(a1.x); ar[5] = splat2(a1.y);
            ar[6] = splat2(a1.z); ar[7] = splat2(a1.w);
            #pragma unroll
            for (int i = 0; i < 8; i++) {
                fma2(acc[i][0], ar[i], w0);
                fma2(acc[i][1], ar[i], w1);
                fma2(acc[i][2], ar[i], w2);
                fma2(acc[i][3], ar[i], w3);
            }
        }
        __syncthreads();
    }

    #pragma unroll
    for (int i = 0; i < 8; i++) {
        int row = row0 + ty * 8 + i;
        if (row < N_NODES) {
            float* cp = &g_h[(size_t)row * N_DIMS + tx * 8];
            float2 c0 = unpack2(acc[i][0]);
            float2 c1 = unpack2(acc[i][1]);
            float2 c2 = unpack2(acc[i][2]);
            float2 c3 = unpack2(acc[i][3]);
            *(float4*)(cp + 0) = make_float4(c0.x, c0.y, c1.x, c1.y);
            *(float4*)(cp + 4) = make_float4(c2.x, c2.y, c3.x, c3.y);
        }
    }
}

// ---------------- aggregation: g_a[n] = relu(b + sum_in norm*h[row]) -------
// one warp per destination node; includes self-loop term dinv[n]^2 * h[n]
__global__ void agg_kernel(const float* __restrict__ bias) {
    int warp = (blockIdx.x * blockDim.x + threadIdx.x) >> 5;
    if (warp >= N_NODES) return;
    int lane = threadIdx.x & 31;

    const float* h = (const float*)g_h;
    float dv = g_dinv[warp];
    float s  = dv * dv;
    const float4* hn = (const float4*)(h + (size_t)warp * N_DIMS);
    float4 v0 = hn[lane], v1 = hn[lane + 32];
    float4 a0 = make_float4(v0.x * s, v0.y * s, v0.z * s, v0.w * s);
    float4 a1 = make_float4(v1.x * s, v1.y * s, v1.z * s, v1.w * s);

    int beg = g_rowptr[warp], end = g_rowptr[warp + 1];
    for (int k = beg; k < end; ++k) {
        int e    = g_eidx[k];
        float nm = g_norm[e];
        const float4* hr = (const float4*)(h + (size_t)g_row[e] * N_DIMS);
        float4 u0 = hr[lane], u1 = hr[lane + 32];
        a0.x += nm * u0.x; a0.y += nm * u0.y; a0.z += nm * u0.z; a0.w += nm * u0.w;
        a1.x += nm * u1.x; a1.y += nm * u1.y; a1.z += nm * u1.z; a1.w += nm * u1.w;
    }

    float4 b0 = ((const float4*)bias)[lane];
    float4 b1 = ((const float4*)bias)[lane + 32];
    float4 o0 = make_float4(fmaxf(a0.x + b0.x, 0.f), fmaxf(a0.y + b0.y, 0.f),
                            fmaxf(a0.z + b0.z, 0.f), fmaxf(a0.w + b0.w, 0.f));
    float4 o1 = make_float4(fmaxf(a1.x + b1.x, 0.f), fmaxf(a1.y + b1.y, 0.f),
                            fmaxf(a1.z + b1.z, 0.f), fmaxf(a1.w + b1.w, 0.f));
    float4* op = (float4*)((float*)g_a + (size_t)warp * N_DIMS);
    op[lane]      = o0;
    op[lane + 32] = o1;
}

// ---------------- classifier: out[M,10] = g_a @ Wc + bc --------------------
__global__ void classify_kernel(const float* __restrict__ Wc,
                                const float* __restrict__ bc,
                                float* __restrict__ out) {
    __shared__ float sW[N_CLSS * N_DIMS];   // transposed: [c][k]
    __shared__ float sb[N_CLSS];
    for (int i = threadIdx.x; i < N_CLSS * N_DIMS; i += blockDim.x) {
        int k = i / N_CLSS, c = i % N_CLSS;
        sW[c * N_DIMS + k] = Wc[i];
    }
    if (threadIdx.x < N_CLSS) sb[threadIdx.x] = bc[threadIdx.x];
    __syncthreads();

    int warp = threadIdx.x >> 5;
    int lane = threadIdx.x & 31;
    int row  = blockIdx.x * 8 + warp;
    if (row >= N_NODES) return;

    const float* ar = (const float*)g_a + (size_t)row * N_DIMS;
    float p[N_CLSS];
    #pragma unroll
    for (int c = 0; c < N_CLSS; c++) p[c] = 0.f;
    #pragma unroll
    for (int kk = 0; kk < 8; kk++) {
        int k = lane + kk * 32;
        float a = ar[k];
        #pragma unroll
        for (int c = 0; c < N_CLSS; c++) p[c] += a * sW[c * N_DIMS + k];
    }
    #pragma unroll
    for (int c = 0; c < N_CLSS; c++) {
        float v = p[c];
        #pragma unroll
        for (int off = 16; off > 0; off >>= 1)
            v += __shfl_down_sync(0xffffffffu, v, off);
        if (lane == 0) out[(size_t)row * N_CLSS + c] = v + sb[c];
    }
}

// ---------------- launch ----------------------------------------------------
extern "C" void kernel_launch(void* const* d_in, const int* in_sizes, int n_in,
                              void* d_out, int out_size) {
    const float* x  = (const float*)d_in[0];
    const int*   ei = (const int*)d_in[1];
    const float* ew = (const float*)d_in[2];
    const float* W1 = (const float*)d_in[3];
    const float* b1 = (const float*)d_in[4];
    const float* W2 = (const float*)d_in[5];
    const float* b2 = (const float*)d_in[6];
    const float* Wc = (const float*)d_in[7];
    const float* bc = (const float*)d_in[8];
    float* out = (float*)d_out;

    const int TB = 256;
    const int gN = (N_NODES + TB - 1) / TB;
    const int gE = (N_EDGES + TB - 1) / TB;

    // --- normalization + CSR build ---
    init_kernel<<<gN, TB>>>();
    edge_pass1<<<gE, TB>>>(ei, ew);
    dinv_kernel<<<gN, TB>>>();
    norm_kernel<<<gE, TB>>>(ew);
    scanA_kernel<<<SCAN_NBLK, 256>>>();
    scanB_kernel<<<1, 1>>>(SCAN_NBLK);
    scanC_kernel<<<gN, TB>>>();
    edge_pass2<<<gE, TB>>>();

    const int gemmGrid = (N_NODES + 63) / 64;      // 1563
    const int aggGrid  = (N_NODES * 32 + TB - 1) / TB;   // warp per node

    // --- layer 1 ---
    gemm_kernel<N_FEAT, 0><<<gemmGrid, 256>>>(x, W1);    // g_h = x @ W1
    agg_kernel<<<aggGrid, TB>>>(b1);                     // g_a = relu(agg + b1)

    // --- layer 2 ---
    gemm_kernel<N_DIMS, 1><<<gemmGrid, 256>>>(nullptr, W2);  // g_h = g_a @ W2
    agg_kernel<<<aggGrid, TB>>>(b2);                         // g_a = relu(agg + b2)

    // --- classifier ---
    classify_kernel<<<(N_NODES + 7) / 8, 256>>>(Wc, bc, out);
}